// round 16
// baseline (speedup 1.0000x reference)
#include <cuda_runtime.h>
#include <cuda_bf16.h>
#include <cstdint>

#define BB 4
#define NPTS 16384
#define NT 512
#define NTILES 2048

__device__ float g_P[BB * NPTS * 128];     // per-point: feat(64) | Y1p(64)

// fused SMEM (bytes)
#define SM_B    0          // 71680: L2(hi|lo) L3(hi|lo) L4(hi|lo)
#define oBH2 0
#define oBL2 9216
#define oBH3 18432
#define oBL3 27648
#define oBH4 36864
#define oBL4 54272
#define SM_BIAS 71680      // 256 floats
#define SM_W1C  72704      // 5 x 64 floats (w1 cols 0,1,2,67,68)
#define SM_A1   73984      // 128 x 336B
#define SM_A4   116992     // 128 x 528B
#define SM_SCR  184576     // 512 floats
#define SMEM_TOTAL 186624

#define STRIDE_A1 336
#define STRIDE_A4 528

// points SMEM (bytes): sT/sY union | A-tile | B1
#define Q_ST   0                   // sT: 68 x 131 floats = 35632B (sY 128x68x4=34816 fits)
#define Q_AT   35632               // 128 x 336B = 43008
#define Q_B1   78640               // 22528 (B1 hi | lo at +11264)
#define QSMEM  101376

__device__ __forceinline__ uint32_t smem_u32(const void* p) {
    uint32_t a;
    asm("{ .reg .u64 t; cvta.to.shared.u64 t, %1; cvt.u32.u64 %0, t; }" : "=r"(a) : "l"(p));
    return a;
}
#define GBAR(id) asm volatile("bar.sync %0, 128;" :: "r"(id) : "memory")
#define LDSM4(r0, r1, r2, r3, addr) \
    asm volatile("ldmatrix.sync.aligned.m8n8.x4.shared.b16 {%0,%1,%2,%3}, [%4];" \
                 : "=r"(r0), "=r"(r1), "=r"(r2), "=r"(r3) : "r"(addr))
#define MMA16816(c, a0, a1, a2, a3, b0, b1) \
    asm volatile("mma.sync.aligned.m16n8k16.row.col.f32.bf16.bf16.f32 " \
                 "{%0,%1,%2,%3}, {%4,%5,%6,%7}, {%8,%9}, {%0,%1,%2,%3};" \
                 : "+f"((c)[0]), "+f"((c)[1]), "+f"((c)[2]), "+f"((c)[3]) \
                 : "r"(a0), "r"(a1), "r"(a2), "r"(a3), "r"(b0), "r"(b1))

__device__ __forceinline__ uint32_t pack2(float x, float y) {
    unsigned short a = __bfloat16_as_ushort(__float2bfloat16_rn(x));
    unsigned short b = __bfloat16_as_ushort(__float2bfloat16_rn(y));
    return (uint32_t)a | ((uint32_t)b << 16);
}
__device__ __forceinline__ float lo_of(float x) {
    return x - __bfloat162float(__float2bfloat16_rn(x));
}
__device__ __forceinline__ float lrelu(float v) { return fmaxf(v, 0.1f * v); }
__device__ __forceinline__ void split_store(char* hi, char* lo, float v) {
    float hf = __bfloat162float(__float2bfloat16_rn(v));
    *(unsigned short*)hi = __bfloat16_as_ushort(__float2bfloat16_rn(v));
    *(unsigned short*)lo = __bfloat16_as_ushort(__float2bfloat16_rn(v - hf));
}

// ---------------- shared per-warp GEMM: M=32 rows, N=16 cols (proven) ----------------
__device__ __forceinline__ void run_layer(float* acc, uint32_t aBase, int strideA,
                                          int loAoff, int ksegs,
                                          uint32_t bHi, uint32_t bLo, int strideB,
                                          int lane, int warpPix, int nBase) {
    const int g = lane >> 3, r = lane & 7;
    const int aRow = ((g & 1) << 3) + r, aColB = (g >> 1) << 4;
    const int bRow = ((g >> 1) << 3) + r, bColB = (g & 1) << 4;
    const uint32_t aAddr = aBase + (uint32_t)(warpPix + aRow) * strideA + aColB;
    const uint32_t bhAddr = bHi + (uint32_t)(nBase + bRow) * strideB + bColB;
    const uint32_t blAddr = bLo + (uint32_t)(nBase + bRow) * strideB + bColB;
#pragma unroll
    for (int j = 0; j < ksegs; j++) {
        const uint32_t ja = (uint32_t)(j << 5);
        uint32_t Ah0[4], Ah1[4], Al0[4], Al1[4], Bh[4], Bl[4];
        LDSM4(Ah0[0], Ah0[1], Ah0[2], Ah0[3], aAddr + ja);
        LDSM4(Ah1[0], Ah1[1], Ah1[2], Ah1[3], aAddr + ja + 16u * strideA);
        LDSM4(Al0[0], Al0[1], Al0[2], Al0[3], aAddr + ja + loAoff);
        LDSM4(Al1[0], Al1[1], Al1[2], Al1[3], aAddr + ja + loAoff + 16u * strideA);
        LDSM4(Bh[0], Bh[1], Bh[2], Bh[3], bhAddr + ja);
        LDSM4(Bl[0], Bl[1], Bl[2], Bl[3], blAddr + ja);
#pragma unroll
        for (int nt = 0; nt < 2; nt++) {
            uint32_t bh0 = Bh[nt << 1], bh1 = Bh[(nt << 1) + 1];
            uint32_t bl0 = Bl[nt << 1], bl1 = Bl[(nt << 1) + 1];
            float* c0 = acc + nt * 4;
            float* c1 = acc + 8 + nt * 4;
            MMA16816(c0, Ah0[0], Ah0[1], Ah0[2], Ah0[3], bh0, bh1);
            MMA16816(c1, Ah1[0], Ah1[1], Ah1[2], Ah1[3], bh0, bh1);
            MMA16816(c0, Al0[0], Al0[1], Al0[2], Al0[3], bh0, bh1);
            MMA16816(c1, Al1[0], Al1[1], Al1[2], Al1[3], bh0, bh1);
            MMA16816(c0, Ah0[0], Ah0[1], Ah0[2], Ah0[3], bl0, bl1);
            MMA16816(c1, Ah1[0], Ah1[1], Ah1[2], Ah1[3], bl0, bl1);
        }
    }
}

__device__ __forceinline__ void epi_store(const float* acc, const float* bias,
                                          char* dst, int strideA, int loOffB,
                                          int lane, int warpPix, int nBase) {
    const int r = lane >> 2, nb = (lane & 3) << 1;
#pragma unroll
    for (int mt = 0; mt < 2; mt++) {
        char* p0 = dst + (warpPix + (mt << 4) + r) * strideA;
        char* p1 = p0 + 8 * strideA;
#pragma unroll
        for (int nt = 0; nt < 2; nt++) {
            const float* c = acc + mt * 8 + nt * 4;
            const int n = nBase + (nt << 3) + nb;
            float b0 = bias[n], b1 = bias[n + 1];
            float v00 = lrelu(c[0] + b0), v01 = lrelu(c[1] + b1);
            float v10 = lrelu(c[2] + b0), v11 = lrelu(c[3] + b1);
            *(uint32_t*)(p0 + n * 2)          = pack2(v00, v01);
            *(uint32_t*)(p0 + loOffB + n * 2) = pack2(lo_of(v00), lo_of(v01));
            *(uint32_t*)(p1 + n * 2)          = pack2(v10, v11);
            *(uint32_t*)(p1 + loOffB + n * 2) = pack2(lo_of(v10), lo_of(v11));
        }
    }
}

// ---------------- points: transpose + self-built B1 + tensor-core Y1p -> g_P ----------------
__global__ __launch_bounds__(512, 1)
void points_kernel(const float* __restrict__ xy, const float* __restrict__ feat3d,
                   const float* __restrict__ flow3d, const float* __restrict__ w1) {
    extern __shared__ float psm[];
    float* sT = psm;                           // [c(68)][p(128)] stride 131
    char* sA = (char*)psm + Q_AT;
    char* sB = (char*)psm + Q_B1;              // B1 hi | lo(+11264)
    float* sY = psm;                           // reused after A-build
    const uint32_t s32 = smem_u32(psm);
    const int tid = threadIdx.x, lane = tid & 31, wid = tid >> 5;
    const int b = blockIdx.x >> 7, p0 = (blockIdx.x & 127) << 7;   // 128 pts/block

    // load sT (coalesced)
    const float* f3 = feat3d + (size_t)b * 64 * NPTS + p0;
#pragma unroll
    for (int it = 0; it < 16; it++) {
        int i = it * 512 + tid, c = i >> 7, pt = i & 127;
        sT[c * 131 + pt] = f3[(size_t)c * NPTS + pt];
    }
    if (tid < 256) {
        int c = tid >> 7, pt = tid & 127;
        sT[(64 + c) * 131 + pt] = flow3d[((size_t)b * 2 + c) * NPTS + p0 + pt];
        sT[(66 + c) * 131 + pt] = xy[((size_t)b * 2 + c) * NPTS + p0 + pt];
    }
    // build B1 split directly from w1: row n, 88 col-slots (stride 176B)
    // col c: value = c<3 ? w1[n][c] : (4<=c<=69) ? w1[n][c-1] : 0
    for (int i = tid; i < 64 * 88; i += 512) {
        int n = i / 88, c = i - n * 88;
        float v = (c < 3) ? w1[n * 69 + c]
                : (c >= 4 && c <= 69) ? w1[n * 69 + c - 1] : 0.0f;
        int off = n * 176 + c * 2;
        split_store(sB + off, sB + 11264 + off, v);
    }
    __syncthreads();

    // write feat to g_P[:,0:64] (coalesced) + build A-tile
    float* gp = g_P + (size_t)((b << 14) + p0) * 128;
#pragma unroll
    for (int it = 0; it < 16; it++) {
        int i = it * 512 + tid, pt = i >> 6, c = i & 63;
        gp[(pt << 7) + c] = sT[c * 131 + pt];
    }
    {   // A-tile: px = tid&127, colgroup = tid>>7 (20 cols each)
        const int px = tid & 127, cg = tid >> 7;
        char* Ap = sA + px * STRIDE_A1;
#pragma unroll
        for (int cc = 0; cc < 20; cc += 2) {
            const int c0 = cg * 20 + cc, c1 = c0 + 1;
            float v0 = (c0 == 1) ? sT[66 * 131 + px] : (c0 == 2) ? sT[67 * 131 + px]
                     : (c0 >= 4 && c0 < 68) ? sT[(c0 - 4) * 131 + px]
                     : (c0 == 68) ? sT[64 * 131 + px] : (c0 == 69) ? sT[65 * 131 + px] : 0.0f;
            float v1 = (c1 == 1) ? sT[66 * 131 + px] : (c1 == 2) ? sT[67 * 131 + px]
                     : (c1 >= 4 && c1 < 68) ? sT[(c1 - 4) * 131 + px]
                     : (c1 == 68) ? sT[64 * 131 + px] : (c1 == 69) ? sT[65 * 131 + px] : 0.0f;
            *(uint32_t*)(Ap + c0 * 2)       = pack2(v0, v1);
            *(uint32_t*)(Ap + 160 + c0 * 2) = pack2(lo_of(v0), lo_of(v1));
        }
    }
    __syncthreads();   // sT reads done; A/B ready

    // Y1p GEMM: 16 warps = 4 groups(32px) x 4 N-quarters, K=80
    float acc[16];
#pragma unroll
    for (int i = 0; i < 16; i++) acc[i] = 0.0f;
    const int warpPix = (wid >> 2) << 5, nBase = (wid & 3) << 4;
    run_layer(acc, s32 + Q_AT, STRIDE_A1, 160, 5,
              s32 + Q_B1, s32 + Q_B1 + 11264, 176, lane, warpPix, nBase);

    // stage acc -> sY (stride 68; overlays sT — no warp still reads sT)
    {
        const int r = lane >> 2, nb = (lane & 3) << 1;
#pragma unroll
        for (int mt = 0; mt < 2; mt++) {
            float* q0 = sY + (warpPix + (mt << 4) + r) * 68;
            float* q1 = q0 + 8 * 68;
#pragma unroll
            for (int nt = 0; nt < 2; nt++) {
                const float* c = acc + mt * 8 + nt * 4;
                const int n = nBase + (nt << 3) + nb;
                q0[n] = c[0]; q0[n + 1] = c[1];
                q1[n] = c[2]; q1[n + 1] = c[3];
            }
        }
    }
    __syncthreads();
    // drain sY -> g_P[:,64:128] coalesced
#pragma unroll
    for (int it = 0; it < 16; it++) {
        int i = it * 512 + tid, pt = i >> 6, n = i & 63;
        gp[(pt << 7) + 64 + n] = sY[pt * 68 + n];
    }
}

// ---------------- fused: R13 core; weights built in-SMEM from raw w2/w3/wf ----------------
__global__ __launch_bounds__(NT, 1)
void fused_kernel(const float* __restrict__ feat2d, const float* __restrict__ lf2d,
                  const int* __restrict__ nnp,
                  const float* __restrict__ w1, const float* __restrict__ w2,
                  const float* __restrict__ w3, const float* __restrict__ wf,
                  const float* __restrict__ b1, const float* __restrict__ b2,
                  const float* __restrict__ b3, const float* __restrict__ bfin,
                  float* __restrict__ out) {
    extern __shared__ char smem[];
    const uint32_t s32 = smem_u32(smem);
    const int tid = threadIdx.x, lane = tid & 31, wid = tid >> 5;
    const int grp = wid >> 2, warpPix = grp << 5;
    const int nBase = (wid & 3) << 4;
    const int barid = 1 + grp;
    const int t = tid & 127, p32 = t & 31, q = t >> 5;
    const int prow = ((tid >> 7) << 5) + p32;

    {   // one-time: build split weights from raw fp32 (no global scratch round-trip)
        for (int i = tid; i < 64 * 72; i += NT) {          // L2 & L3 (72-col rows)
            int n = i / 72, c = i - n * 72;
            float v2 = (c < 64) ? w2[n * 64 + c] : 0.0f;
            float v3 = (c < 64) ? w3[n * 64 + c] : 0.0f;
            int off = n * 144 + c * 2;
            split_store(smem + SM_B + oBH2 + off, smem + SM_B + oBL2 + off, v2);
            split_store(smem + SM_B + oBH3 + off, smem + SM_B + oBL3 + off, v3);
        }
        for (int i = tid; i < 64 * 136; i += NT) {         // L4 (136-col rows)
            int n = i / 136, c = i - n * 136;
            float v = (c < 128) ? wf[n * 128 + c] : 0.0f;
            int off = n * 272 + c * 2;
            split_store(smem + SM_B + oBH4 + off, smem + SM_B + oBL4 + off, v);
        }
        float* sb = (float*)(smem + SM_BIAS);
        float* wc = (float*)(smem + SM_W1C);
        if (tid < 64) {
            sb[tid] = b1[tid]; sb[64 + tid] = b2[tid];
            sb[128 + tid] = b3[tid]; sb[192 + tid] = bfin[tid];
            wc[tid]       = w1[tid * 69 + 0];
            wc[64 + tid]  = w1[tid * 69 + 1];
            wc[128 + tid] = w1[tid * 69 + 2];
            wc[192 + tid] = w1[tid * 69 + 67];
            wc[256 + tid] = w1[tid * 69 + 68];
        }
    }
    __syncthreads();
    const float* sbias = (const float*)(smem + SM_BIAS);
    const float* w1c = (const float*)(smem + SM_W1C);
    float* scr = (float*)(smem + SM_SCR);

    const uint32_t aA1 = s32 + SM_A1, aA4 = s32 + SM_A4;
    const uint32_t wb = s32 + SM_B;

    for (int tile = blockIdx.x; tile < NTILES; tile += gridDim.x) {
        const int gp = (tile << 7) + prow;
        const int b = gp >> 16, pix = gp & 65535;

        // ---------- prologue ----------
        {
            const int idx = nnp[gp];
            const float* prp = g_P + (size_t)((b << 14) + idx) * 128;
            float av[16];
            const float* t3h = prp + (q << 4);
#pragma unroll
            for (int k = 0; k < 16; k += 4) {
                float4 v = *(const float4*)(t3h + k);
                av[k] = v.x; av[k + 1] = v.y; av[k + 2] = v.z; av[k + 3] = v.w;
            }
            float y1p[16];
            const float4* yp = (const float4*)(prp + 64 + (q << 4));
#pragma unroll
            for (int j4 = 0; j4 < 4; j4++) {
                float4 v = yp[j4];
                y1p[j4 * 4] = v.x; y1p[j4 * 4 + 1] = v.y;
                y1p[j4 * 4 + 2] = v.z; y1p[j4 * 4 + 3] = v.w;
            }
            const float* lf = lf2d + (((size_t)b * 2) << 16) + pix;
            const float lfx = lf[0], lfy = lf[65536];

            char* A4p = smem + SM_A4 + prow * STRIDE_A4;
            const float* f2p = feat2d + (((size_t)(b * 64 + (q << 4))) << 16) + pix;
            float pc = 0.0f;
#pragma unroll
            for (int c = 0; c < 16; c += 2) {
                float v0 = f2p[(size_t)c << 16], v1 = f2p[(size_t)(c + 1) << 16];
                pc += av[c] * v0 + av[c + 1] * v1;
                *(uint32_t*)(A4p + 128 + (q << 5) + c * 2) = pack2(v0, v1);
                *(uint32_t*)(A4p + 384 + (q << 5) + c * 2) = pack2(lo_of(v0), lo_of(v1));
            }
            scr[tid] = pc;
            GBAR(barid);
            const int b0i = (grp << 7) + p32;
            const float corr = (scr[b0i] + scr[b0i + 32] + scr[b0i + 64] + scr[b0i + 96])
                               * (1.0f / 64.0f);
            const float swi = -(float)(pix & 255), shi = -(float)(pix >> 8);

            char* A1p = smem + SM_A1 + prow * STRIDE_A1;
#pragma unroll
            for (int j = 0; j < 16; j += 2) {
                const int c = (q << 4) + j;
                float ya = y1p[j]     + corr * w1c[c]     + swi * w1c[64 + c]
                         + shi * w1c[128 + c]     - lfx * w1c[192 + c]
                         - lfy * w1c[256 + c]     + sbias[c];
                float yb = y1p[j + 1] + corr * w1c[c + 1] + swi * w1c[64 + c + 1]
                         + shi * w1c[128 + c + 1] - lfx * w1c[192 + c + 1]
                         - lfy * w1c[256 + c + 1] + sbias[c + 1];
                ya = lrelu(ya); yb = lrelu(yb);
                *(uint32_t*)(A1p + c * 2)       = pack2(ya, yb);
                *(uint32_t*)(A1p + 128 + c * 2) = pack2(lo_of(ya), lo_of(yb));
            }
        }
        GBAR(barid);

        float acc[16];

        // ---- layer 2 ----
#pragma unroll
        for (int i = 0; i < 16; i++) acc[i] = 0.0f;
        run_layer(acc, aA1, STRIDE_A1, 128, 4,
                  wb + oBH2, wb + oBL2, 144, lane, warpPix, nBase);
        GBAR(barid);
        epi_store(acc, sbias + 64, smem + SM_A1, STRIDE_A1, 128, lane, warpPix, nBase);
        GBAR(barid);

        // ---- layer 3 ----
#pragma unroll
        for (int i = 0; i < 16; i++) acc[i] = 0.0f;
        run_layer(acc, aA1, STRIDE_A1, 128, 4,
                  wb + oBH3, wb + oBL3, 144, lane, warpPix, nBase);
        epi_store(acc, sbias + 128, smem + SM_A4, STRIDE_A4, 256, lane, warpPix, nBase);
        GBAR(barid);

        // ---- layer 4 ----
#pragma unroll
        for (int i = 0; i < 16; i++) acc[i] = 0.0f;
        run_layer(acc, aA4, STRIDE_A4, 256, 8,
                  wb + oBH4, wb + oBL4, 272, lane, warpPix, nBase);

        {
            const int pixbase = (tile << 7) & 65535;
            const int r = lane >> 2, nb = (lane & 3) << 1;
            float* ob = out + ((size_t)b << 22) + pixbase;
#pragma unroll
            for (int mt = 0; mt < 2; mt++) {
                float* p0 = ob + warpPix + (mt << 4) + r;
                float* p1 = p0 + 8;
#pragma unroll
                for (int nt = 0; nt < 2; nt++) {
                    const float* c = acc + mt * 8 + nt * 4;
                    const int n = nBase + (nt << 3) + nb;
                    float bb0 = sbias[192 + n], bb1 = sbias[192 + n + 1];
                    p0[(size_t)n << 16] = lrelu(c[0] + bb0);
                    p0[(size_t)(n + 1) << 16] = lrelu(c[1] + bb1);
                    p1[(size_t)n << 16] = lrelu(c[2] + bb0);
                    p1[(size_t)(n + 1) << 16] = lrelu(c[3] + bb1);
                }
            }
        }
        GBAR(barid);
    }
}

extern "C" void kernel_launch(void* const* d_in, const int* in_sizes, int n_in,
                              void* d_out, int out_size) {
    const float* xy   = (const float*)d_in[0];
    const float* f2d  = (const float*)d_in[1];
    const float* f3d  = (const float*)d_in[2];
    const float* lf2d = (const float*)d_in[3];
    const float* lf3d = (const float*)d_in[4];
    const int*   nnp  = (const int*)d_in[5];
    const float* w1 = (const float*)d_in[6];
    const float* b1 = (const float*)d_in[7];
    const float* w2 = (const float*)d_in[8];
    const float* b2 = (const float*)d_in[9];
    const float* w3 = (const float*)d_in[10];
    const float* b3 = (const float*)d_in[11];
    const float* wf = (const float*)d_in[12];
    const float* bf = (const float*)d_in[13];
    float* out = (float*)d_out;

    cudaFuncSetAttribute(points_kernel,
                         cudaFuncAttributeMaxDynamicSharedMemorySize, QSMEM);
    cudaFuncSetAttribute(fused_kernel,
                         cudaFuncAttributeMaxDynamicSharedMemorySize, SMEM_TOTAL);
    points_kernel<<<512, 512, QSMEM>>>(xy, f3d, lf3d, w1);
    fused_kernel<<<148, NT, SMEM_TOTAL>>>(f2d, lf2d, nnp, w1, w2, w3, wf,
                                          b1, b2, b3, bf, out);
}

// round 17
// speedup vs baseline: 1.0516x; 1.0516x over previous
#include <cuda_runtime.h>
#include <cuda_bf16.h>
#include <cstdint>

#define BB 4
#define NPTS 16384
#define NT 512
#define NTILES 2048
#define NCHUNKS 512
#define GRID 148

__device__ float g_P[BB * NPTS * 128];     // per-point: feat(64) | Y1p(64)
__device__ unsigned int g_arrive = 0;      // monotonic grid-barrier counter

// fused SMEM (bytes)
#define SM_B    0          // 71680: during points = B1(hi|lo+11264); after barrier = L2|L3|L4
#define oBH2 0
#define oBL2 9216
#define oBH3 18432
#define oBL3 27648
#define oBH4 36864
#define oBL4 54272
#define SM_BIAS 71680      // 256 floats
#define SM_W1C  72704      // 5 x 64 floats
#define SM_A1   73984      // 128 x 336B   (points: sA; tiles: A1)
#define SM_A4   116992     // 128 x 528B   (points: sT/sY; tiles: A4)
#define SM_SCR  184576     // 512 floats
#define SMEM_TOTAL 186624

#define STRIDE_A1 336
#define STRIDE_A4 528

__device__ __forceinline__ uint32_t smem_u32(const void* p) {
    uint32_t a;
    asm("{ .reg .u64 t; cvta.to.shared.u64 t, %1; cvt.u32.u64 %0, t; }" : "=r"(a) : "l"(p));
    return a;
}
#define GBAR(id) asm volatile("bar.sync %0, 128;" :: "r"(id) : "memory")
#define LDSM4(r0, r1, r2, r3, addr) \
    asm volatile("ldmatrix.sync.aligned.m8n8.x4.shared.b16 {%0,%1,%2,%3}, [%4];" \
                 : "=r"(r0), "=r"(r1), "=r"(r2), "=r"(r3) : "r"(addr))
#define MMA16816(c, a0, a1, a2, a3, b0, b1) \
    asm volatile("mma.sync.aligned.m16n8k16.row.col.f32.bf16.bf16.f32 " \
                 "{%0,%1,%2,%3}, {%4,%5,%6,%7}, {%8,%9}, {%0,%1,%2,%3};" \
                 : "+f"((c)[0]), "+f"((c)[1]), "+f"((c)[2]), "+f"((c)[3]) \
                 : "r"(a0), "r"(a1), "r"(a2), "r"(a3), "r"(b0), "r"(b1))

__device__ __forceinline__ uint32_t pack2(float x, float y) {
    unsigned short a = __bfloat16_as_ushort(__float2bfloat16_rn(x));
    unsigned short b = __bfloat16_as_ushort(__float2bfloat16_rn(y));
    return (uint32_t)a | ((uint32_t)b << 16);
}
__device__ __forceinline__ float lo_of(float x) {
    return x - __bfloat162float(__float2bfloat16_rn(x));
}
__device__ __forceinline__ float lrelu(float v) { return fmaxf(v, 0.1f * v); }
// paired split store: two adjacent cols -> one u32 to hi region + one u32 to lo region
__device__ __forceinline__ void split_store2(char* hi, char* lo, float v0, float v1) {
    *(uint32_t*)hi = pack2(v0, v1);
    *(uint32_t*)lo = pack2(lo_of(v0), lo_of(v1));
}

// ---------------- per-warp GEMM: M=32 rows, N=16 cols (proven) ----------------
__device__ __forceinline__ void run_layer(float* acc, uint32_t aBase, int strideA,
                                          int loAoff, int ksegs,
                                          uint32_t bHi, uint32_t bLo, int strideB,
                                          int lane, int warpPix, int nBase) {
    const int g = lane >> 3, r = lane & 7;
    const int aRow = ((g & 1) << 3) + r, aColB = (g >> 1) << 4;
    const int bRow = ((g >> 1) << 3) + r, bColB = (g & 1) << 4;
    const uint32_t aAddr = aBase + (uint32_t)(warpPix + aRow) * strideA + aColB;
    const uint32_t bhAddr = bHi + (uint32_t)(nBase + bRow) * strideB + bColB;
    const uint32_t blAddr = bLo + (uint32_t)(nBase + bRow) * strideB + bColB;
#pragma unroll
    for (int j = 0; j < ksegs; j++) {
        const uint32_t ja = (uint32_t)(j << 5);
        uint32_t Ah0[4], Ah1[4], Al0[4], Al1[4], Bh[4], Bl[4];
        LDSM4(Ah0[0], Ah0[1], Ah0[2], Ah0[3], aAddr + ja);
        LDSM4(Ah1[0], Ah1[1], Ah1[2], Ah1[3], aAddr + ja + 16u * strideA);
        LDSM4(Al0[0], Al0[1], Al0[2], Al0[3], aAddr + ja + loAoff);
        LDSM4(Al1[0], Al1[1], Al1[2], Al1[3], aAddr + ja + loAoff + 16u * strideA);
        LDSM4(Bh[0], Bh[1], Bh[2], Bh[3], bhAddr + ja);
        LDSM4(Bl[0], Bl[1], Bl[2], Bl[3], blAddr + ja);
#pragma unroll
        for (int nt = 0; nt < 2; nt++) {
            uint32_t bh0 = Bh[nt << 1], bh1 = Bh[(nt << 1) + 1];
            uint32_t bl0 = Bl[nt << 1], bl1 = Bl[(nt << 1) + 1];
            float* c0 = acc + nt * 4;
            float* c1 = acc + 8 + nt * 4;
            MMA16816(c0, Ah0[0], Ah0[1], Ah0[2], Ah0[3], bh0, bh1);
            MMA16816(c1, Ah1[0], Ah1[1], Ah1[2], Ah1[3], bh0, bh1);
            MMA16816(c0, Al0[0], Al0[1], Al0[2], Al0[3], bh0, bh1);
            MMA16816(c1, Al1[0], Al1[1], Al1[2], Al1[3], bh0, bh1);
            MMA16816(c0, Ah0[0], Ah0[1], Ah0[2], Ah0[3], bl0, bl1);
            MMA16816(c1, Ah1[0], Ah1[1], Ah1[2], Ah1[3], bl0, bl1);
        }
    }
}

__device__ __forceinline__ void epi_store(const float* acc, const float* bias,
                                          char* dst, int strideA, int loOffB,
                                          int lane, int warpPix, int nBase) {
    const int r = lane >> 2, nb = (lane & 3) << 1;
#pragma unroll
    for (int mt = 0; mt < 2; mt++) {
        char* p0 = dst + (warpPix + (mt << 4) + r) * strideA;
        char* p1 = p0 + 8 * strideA;
#pragma unroll
        for (int nt = 0; nt < 2; nt++) {
            const float* c = acc + mt * 8 + nt * 4;
            const int n = nBase + (nt << 3) + nb;
            float b0 = bias[n], b1 = bias[n + 1];
            float v00 = lrelu(c[0] + b0), v01 = lrelu(c[1] + b1);
            float v10 = lrelu(c[2] + b0), v11 = lrelu(c[3] + b1);
            *(uint32_t*)(p0 + n * 2)          = pack2(v00, v01);
            *(uint32_t*)(p0 + loOffB + n * 2) = pack2(lo_of(v00), lo_of(v01));
            *(uint32_t*)(p1 + n * 2)          = pack2(v10, v11);
            *(uint32_t*)(p1 + loOffB + n * 2) = pack2(lo_of(v10), lo_of(v11));
        }
    }
}

// ---------------- single persistent kernel ----------------
__global__ __launch_bounds__(NT, 1)
void fused_kernel(const float* __restrict__ xy, const float* __restrict__ feat2d,
                  const float* __restrict__ feat3d, const float* __restrict__ lf2d,
                  const float* __restrict__ flow3d, const int* __restrict__ nnp,
                  const float* __restrict__ w1, const float* __restrict__ w2,
                  const float* __restrict__ w3, const float* __restrict__ wf,
                  const float* __restrict__ b1, const float* __restrict__ b2,
                  const float* __restrict__ b3, const float* __restrict__ bfin,
                  float* __restrict__ out) {
    extern __shared__ char smem[];
    const uint32_t s32 = smem_u32(smem);
    const int tid = threadIdx.x, lane = tid & 31, wid = tid >> 5;

    // ---- bias + w1 per-pixel cols (regions untouched by points phase) ----
    {
        float* sb = (float*)(smem + SM_BIAS);
        float* wc = (float*)(smem + SM_W1C);
        if (tid < 64) {
            sb[tid] = b1[tid]; sb[64 + tid] = b2[tid];
            sb[128 + tid] = b3[tid]; sb[192 + tid] = bfin[tid];
            wc[tid]       = w1[tid * 69 + 0];
            wc[64 + tid]  = w1[tid * 69 + 1];
            wc[128 + tid] = w1[tid * 69 + 2];
            wc[192 + tid] = w1[tid * 69 + 67];
            wc[256 + tid] = w1[tid * 69 + 68];
        }
    }

    // ================= PHASE 1: points (Y1p precompute) =================
    {
        // B1 split (64 x 88-col rows, stride 176B) from w1, built once in SM_B
        for (int i = tid; i < 64 * 44; i += NT) {
            int n = i / 44, cp = (i - n * 44) << 1;    // cols cp, cp+1
            float v0 = (cp < 3) ? w1[n * 69 + cp]
                     : (cp >= 4 && cp <= 69) ? w1[n * 69 + cp - 1] : 0.0f;
            int c1 = cp + 1;
            float v1 = (c1 < 3) ? w1[n * 69 + c1]
                     : (c1 >= 4 && c1 <= 69) ? w1[n * 69 + c1 - 1] : 0.0f;
            int off = n * 176 + cp * 2;
            split_store2(smem + SM_B + off, smem + SM_B + 11264 + off, v0, v1);
        }
        __syncthreads();

        float* sT = (float*)(smem + SM_A4);            // [c(68)][p(128)] stride 131
        char* sA = smem + SM_A1;
        float* sY = (float*)(smem + SM_A4);            // reused post-GEMM

        for (int ck = blockIdx.x; ck < NCHUNKS; ck += GRID) {
            const int pb = ck >> 7, p0 = (ck & 127) << 7;
            const float* f3 = feat3d + (size_t)pb * 64 * NPTS + p0;
#pragma unroll
            for (int it = 0; it < 16; it++) {
                int i = it * 512 + tid, c = i >> 7, pt = i & 127;
                sT[c * 131 + pt] = f3[(size_t)c * NPTS + pt];
            }
            if (tid < 256) {
                int c = tid >> 7, pt = tid & 127;
                sT[(64 + c) * 131 + pt] = flow3d[((size_t)pb * 2 + c) * NPTS + p0 + pt];
                sT[(66 + c) * 131 + pt] = xy[((size_t)pb * 2 + c) * NPTS + p0 + pt];
            }
            __syncthreads();

            float* gpp = g_P + (size_t)((pb << 14) + p0) * 128;
#pragma unroll
            for (int it = 0; it < 16; it++) {
                int i = it * 512 + tid, pt = i >> 6, c = i & 63;
                gpp[(pt << 7) + c] = sT[c * 131 + pt];
            }
            {   // A-tile: px = tid&127, colgroup = tid>>7 (20 cols)
                const int px = tid & 127, cg = tid >> 7;
                char* Ap = sA + px * STRIDE_A1;
#pragma unroll
                for (int cc = 0; cc < 20; cc += 2) {
                    const int c0 = cg * 20 + cc, c1 = c0 + 1;
                    float v0 = (c0 == 1) ? sT[66 * 131 + px] : (c0 == 2) ? sT[67 * 131 + px]
                             : (c0 >= 4 && c0 < 68) ? sT[(c0 - 4) * 131 + px]
                             : (c0 == 68) ? sT[64 * 131 + px]
                             : (c0 == 69) ? sT[65 * 131 + px] : 0.0f;
                    float v1 = (c1 == 1) ? sT[66 * 131 + px] : (c1 == 2) ? sT[67 * 131 + px]
                             : (c1 >= 4 && c1 < 68) ? sT[(c1 - 4) * 131 + px]
                             : (c1 == 68) ? sT[64 * 131 + px]
                             : (c1 == 69) ? sT[65 * 131 + px] : 0.0f;
                    *(uint32_t*)(Ap + c0 * 2)       = pack2(v0, v1);
                    *(uint32_t*)(Ap + 160 + c0 * 2) = pack2(lo_of(v0), lo_of(v1));
                }
            }
            __syncthreads();

            float acc[16];
#pragma unroll
            for (int i = 0; i < 16; i++) acc[i] = 0.0f;
            run_layer(acc, s32 + SM_A1, STRIDE_A1, 160, 5,
                      s32 + SM_B, s32 + SM_B + 11264, 176,
                      lane, (wid >> 2) << 5, (wid & 3) << 4);
            // GEMM reads sA/sB; staging writes sT region (disjoint) -> no sync needed
            {
                const int r = lane >> 2, nb = (lane & 3) << 1;
                const int warpPix = (wid >> 2) << 5, nBase = (wid & 3) << 4;
#pragma unroll
                for (int mt = 0; mt < 2; mt++) {
                    float* q0 = sY + (warpPix + (mt << 4) + r) * 68;
                    float* q1 = q0 + 8 * 68;
#pragma unroll
                    for (int nt = 0; nt < 2; nt++) {
                        const float* c = acc + mt * 8 + nt * 4;
                        const int n = nBase + (nt << 3) + nb;
                        q0[n] = c[0]; q0[n + 1] = c[1];
                        q1[n] = c[2]; q1[n + 1] = c[3];
                    }
                }
            }
            __syncthreads();
#pragma unroll
            for (int it = 0; it < 16; it++) {
                int i = it * 512 + tid, pt = i >> 6, n = i & 63;
                gpp[(pt << 7) + 64 + n] = sY[pt * 68 + n];
            }
            __syncthreads();   // drain done before next chunk overwrites sT
        }
    }

    // ================= grid-wide barrier (all 148 CTAs co-resident) =================
    __threadfence();
    __syncthreads();
    if (tid == 0) {
        unsigned int my = atomicAdd(&g_arrive, 1u);
        unsigned int target = (my / (unsigned)GRID + 1u) * (unsigned)GRID;
        while (atomicAdd(&g_arrive, 0u) < target) { }
    }
    __syncthreads();
    __threadfence();

    // ================= PHASE 2: build L2-L4 split weights in SM_B =================
    {
        for (int i = tid; i < 64 * 36; i += NT) {          // L2 & L3: 36 col-pairs/row
            int n = i / 36, cp = (i - n * 36) << 1;
            float a2 = (cp < 64) ? w2[n * 64 + cp] : 0.0f;
            float b2v = (cp + 1 < 64) ? w2[n * 64 + cp + 1] : 0.0f;
            float a3 = (cp < 64) ? w3[n * 64 + cp] : 0.0f;
            float b3v = (cp + 1 < 64) ? w3[n * 64 + cp + 1] : 0.0f;
            int off = n * 144 + cp * 2;
            split_store2(smem + SM_B + oBH2 + off, smem + SM_B + oBL2 + off, a2, b2v);
            split_store2(smem + SM_B + oBH3 + off, smem + SM_B + oBL3 + off, a3, b3v);
        }
        for (int i = tid; i < 64 * 68; i += NT) {          // L4: 68 col-pairs/row
            int n = i / 68, cp = (i - n * 68) << 1;
            float a4 = (cp < 128) ? wf[n * 128 + cp] : 0.0f;
            float b4 = (cp + 1 < 128) ? wf[n * 128 + cp + 1] : 0.0f;
            int off = n * 272 + cp * 2;
            split_store2(smem + SM_B + oBH4 + off, smem + SM_B + oBL4 + off, a4, b4);
        }
    }
    __syncthreads();

    // ================= PHASE 3: tile loop (proven R13 core) =================
    const float* sbias = (const float*)(smem + SM_BIAS);
    const float* w1c = (const float*)(smem + SM_W1C);
    float* scr = (float*)(smem + SM_SCR);
    const int grp = wid >> 2, warpPix = grp << 5;
    const int nBase = (wid & 3) << 4;
    const int barid = 1 + grp;
    const int t = tid & 127, p32 = t & 31, q = t >> 5;
    const int prow = ((tid >> 7) << 5) + p32;
    const uint32_t aA1 = s32 + SM_A1, aA4 = s32 + SM_A4;
    const uint32_t wb = s32 + SM_B;

    for (int tile = blockIdx.x; tile < NTILES; tile += GRID) {
        const int gp = (tile << 7) + prow;
        const int b = gp >> 16, pix = gp & 65535;

        {   // prologue
            const int idx = nnp[gp];
            const float* prp = g_P + (size_t)((b << 14) + idx) * 128;
            float av[16];
            const float* t3h = prp + (q << 4);
#pragma unroll
            for (int k = 0; k < 16; k += 4) {
                float4 v = *(const float4*)(t3h + k);
                av[k] = v.x; av[k + 1] = v.y; av[k + 2] = v.z; av[k + 3] = v.w;
            }
            float y1p[16];
            const float4* yp = (const float4*)(prp + 64 + (q << 4));
#pragma unroll
            for (int j4 = 0; j4 < 4; j4++) {
                float4 v = yp[j4];
                y1p[j4 * 4] = v.x; y1p[j4 * 4 + 1] = v.y;
                y1p[j4 * 4 + 2] = v.z; y1p[j4 * 4 + 3] = v.w;
            }
            const float* lf = lf2d + (((size_t)b * 2) << 16) + pix;
            const float lfx = lf[0], lfy = lf[65536];

            char* A4p = smem + SM_A4 + prow * STRIDE_A4;
            const float* f2p = feat2d + (((size_t)(b * 64 + (q << 4))) << 16) + pix;
            float pc = 0.0f;
#pragma unroll
            for (int c = 0; c < 16; c += 2) {
                float v0 = f2p[(size_t)c << 16], v1 = f2p[(size_t)(c + 1) << 16];
                pc += av[c] * v0 + av[c + 1] * v1;
                *(uint32_t*)(A4p + 128 + (q << 5) + c * 2) = pack2(v0, v1);
                *(uint32_t*)(A4p + 384 + (q << 5) + c * 2) = pack2(lo_of(v0), lo_of(v1));
            }
            scr[tid] = pc;
            GBAR(barid);
            const int b0i = (grp << 7) + p32;
            const float corr = (scr[b0i] + scr[b0i + 32] + scr[b0i + 64] + scr[b0i + 96])
                               * (1.0f / 64.0f);
            const float swi = -(float)(pix & 255), shi = -(float)(pix >> 8);

            char* A1p = smem + SM_A1 + prow * STRIDE_A1;
#pragma unroll
            for (int j = 0; j < 16; j += 2) {
                const int c = (q << 4) + j;
                float ya = y1p[j]     + corr * w1c[c]     + swi * w1c[64 + c]
                         + shi * w1c[128 + c]     - lfx * w1c[192 + c]
                         - lfy * w1c[256 + c]     + sbias[c];
                float yb = y1p[j + 1] + corr * w1c[c + 1] + swi * w1c[64 + c + 1]
                         + shi * w1c[128 + c + 1] - lfx * w1c[192 + c + 1]
                         - lfy * w1c[256 + c + 1] + sbias[c + 1];
                ya = lrelu(ya); yb = lrelu(yb);
                *(uint32_t*)(A1p + c * 2)       = pack2(ya, yb);
                *(uint32_t*)(A1p + 128 + c * 2) = pack2(lo_of(ya), lo_of(yb));
            }
        }
        GBAR(barid);

        float acc[16];

        // ---- layer 2 ----
#pragma unroll
        for (int i = 0; i < 16; i++) acc[i] = 0.0f;
        run_layer(acc, aA1, STRIDE_A1, 128, 4,
                  wb + oBH2, wb + oBL2, 144, lane, warpPix, nBase);
        GBAR(barid);
        epi_store(acc, sbias + 64, smem + SM_A1, STRIDE_A1, 128, lane, warpPix, nBase);
        GBAR(barid);

        // ---- layer 3 ----
#pragma unroll
        for (int i = 0; i < 16; i++) acc[i] = 0.0f;
        run_layer(acc, aA1, STRIDE_A1, 128, 4,
                  wb + oBH3, wb + oBL3, 144, lane, warpPix, nBase);
        epi_store(acc, sbias + 128, smem + SM_A4, STRIDE_A4, 256, lane, warpPix, nBase);
        GBAR(barid);

        // ---- layer 4 ----
#pragma unroll
        for (int i = 0; i < 16; i++) acc[i] = 0.0f;
        run_layer(acc, aA4, STRIDE_A4, 256, 8,
                  wb + oBH4, wb + oBL4, 272, lane, warpPix, nBase);

        {   // output
            const int pixbase = (tile << 7) & 65535;
            const int r = lane >> 2, nb = (lane & 3) << 1;
            float* ob = out + ((size_t)b << 22) + pixbase;
#pragma unroll
            for (int mt = 0; mt < 2; mt++) {
                float* p0 = ob + warpPix + (mt << 4) + r;
                float* p1 = p0 + 8;
#pragma unroll
                for (int nt = 0; nt < 2; nt++) {
                    const float* c = acc + mt * 8 + nt * 4;
                    const int n = nBase + (nt << 3) + nb;
                    float bb0 = sbias[192 + n], bb1 = sbias[192 + n + 1];
                    p0[(size_t)n << 16] = lrelu(c[0] + bb0);
                    p0[(size_t)(n + 1) << 16] = lrelu(c[1] + bb1);
                    p1[(size_t)n << 16] = lrelu(c[2] + bb0);
                    p1[(size_t)(n + 1) << 16] = lrelu(c[3] + bb1);
                }
            }
        }
        GBAR(barid);
    }
}

extern "C" void kernel_launch(void* const* d_in, const int* in_sizes, int n_in,
                              void* d_out, int out_size) {
    const float* xy   = (const float*)d_in[0];
    const float* f2d  = (const float*)d_in[1];
    const float* f3d  = (const float*)d_in[2];
    const float* lf2d = (const float*)d_in[3];
    const float* lf3d = (const float*)d_in[4];
    const int*   nnp  = (const int*)d_in[5];
    const float* w1 = (const float*)d_in[6];
    const float* b1 = (const float*)d_in[7];
    const float* w2 = (const float*)d_in[8];
    const float* b2 = (const float*)d_in[9];
    const float* w3 = (const float*)d_in[10];
    const float* b3 = (const float*)d_in[11];
    const float* wf = (const float*)d_in[12];
    const float* bf = (const float*)d_in[13];
    float* out = (float*)d_out;

    cudaFuncSetAttribute(fused_kernel,
                         cudaFuncAttributeMaxDynamicSharedMemorySize, SMEM_TOTAL);
    fused_kernel<<<GRID, NT, SMEM_TOTAL>>>(xy, f2d, f3d, lf2d, lf3d, nnp,
                                           w1, w2, w3, wf, b1, b2, b3, bf, out);
}